// round 15
// baseline (speedup 1.0000x reference)
#include <cuda_runtime.h>
#include <cstdint>

// ---------------------------------------------------------------------------
// SPNet, v14: round-13 static structure + in-kernel opportunistic drain.
//
// Round-14 lesson: dynamic persistent tile loop kills streaming MLP (atomic->
// barrier->loads per iteration). Round-13 lesson: a trailing kernel costs a
// fixed ~11us regardless of its work. So: ONE kernel, static tiles (proven
// 16xfloat4 __ldcs shape untouched), and leftover tiles drained in-kernel:
// each finishing block makes one NON-BLOCKING pop attempt (sentinel-exchange,
// exclusive); the provably-last gather block sweeps orphans until
// painted == published. Only the last block ever waits (queue final by then).
// ---------------------------------------------------------------------------

#define BATCH    16
#define HW       160000         // 400*400
#define HW4      40000          // float4 per plane
#define GB_PER_B 157            // ceil(40000/256)
#define NGATHER  (BATCH * GB_PER_B)   // 2512
#define NCONVBLK 64
#define NTHREADS 256
#define SENT     0xFFFFFFFFu

// g_sync layout
#define SC1    0    // [0:16)  conv1 quarter counts
#define SC2    16   // [16:32) conv2 quarter counts
#define SPR    32   // [32:48) per-batch palette-ready
#define SRESV  48   // published entry count
#define SFIN   49   // gather blocks finished their tile
#define SDEQ   50   // pop tickets
#define SPAINT 51   // painted entry count
#define SPALL  52   // palettes published (== BATCH when all ready)
#define QBASE  53

__device__ float              g_h1[BATCH * 6  * 64 * 64];
__device__ float              g_h2[BATCH * 12 * 32 * 32];
__device__ float              g_pal[BATCH * 48];
__device__ unsigned long long g_mask[BATCH * HW4];
__device__ unsigned           g_sync[QBASE + NGATHER];

__device__ __forceinline__ float leaky(float v) {
    return (v >= 0.f) ? v : 0.01f * v;
}

__global__ void __launch_bounds__(NTHREADS, 2)
spnet_main_kernel(const float* __restrict__ x,
                  const float* __restrict__ logits,
                  const float* __restrict__ w1, const float* __restrict__ b1,
                  const float* __restrict__ w2, const float* __restrict__ b2,
                  const float* __restrict__ w3, const float* __restrict__ b3,
                  const float* __restrict__ w4, const float* __restrict__ b4,
                  const float* __restrict__ w5, const float* __restrict__ b5,
                  const float* __restrict__ w6, const float* __restrict__ b6,
                  float* __restrict__ out) {
    const int bid = blockIdx.x;
    const int tid = threadIdx.x;

    // ---------------------------------------------------------------------
    // CONV PATH (blocks 0..63) — byte-identical to the 46.8us version,
    // plus an SPALL increment after palette publish.
    // ---------------------------------------------------------------------
    if (bid < NCONVBLK) {
        const int b = bid >> 2;
        const int q = bid & 3;

        __shared__ float sw1[162], sb1[6];
        __shared__ float sw2[648], sb2[12];
        __shared__ float sw3[1296], sb3[12];
        __shared__ float sw4[1296], sb4[12];
        __shared__ float sw5[648], sb5[6];
        __shared__ float sw6[18], sb6[3];
        __shared__ float h3[12 * 16 * 16];
        __shared__ float h4[12 * 8 * 8];
        __shared__ float h5[6 * 16];

        for (int i = tid; i < 162; i += NTHREADS) sw1[i] = w1[i];
        for (int i = tid; i < 648; i += NTHREADS) { sw2[i] = w2[i]; sw5[i] = w5[i]; }
        for (int i = tid; i < 1296; i += NTHREADS) { sw3[i] = w3[i]; sw4[i] = w4[i]; }
        if (tid < 18) sw6[tid] = w6[tid];
        if (tid < 12) { sb2[tid] = b2[tid]; sb3[tid] = b3[tid]; sb4[tid] = b4[tid]; }
        if (tid < 6)  { sb1[tid] = b1[tid]; sb5[tid] = b5[tid]; }
        if (tid < 3)  sb6[tid] = b6[tid];
        __syncthreads();

        // conv1, quarter q
        for (int pos = tid; pos < 1024; pos += NTHREADS) {
            const int i = q * 16 + (pos >> 6);
            const int j = pos & 63;
            float acc[6];
#pragma unroll
            for (int oc = 0; oc < 6; oc++) acc[oc] = sb1[oc];
#pragma unroll
            for (int ic = 0; ic < 3; ic++) {
                const float* xp = x + (size_t)(b * 3 + ic) * HW;
#pragma unroll
                for (int di = 0; di < 3; di++) {
                    const int yi = 2 * i + di - 1;
#pragma unroll
                    for (int dj = 0; dj < 3; dj++) {
                        const int yj = 2 * j + dj - 1;
                        float v = 0.f;
                        if (yi >= 0 && yj >= 0) v = xp[yi * 400 + yj];
#pragma unroll
                        for (int oc = 0; oc < 6; oc++)
                            acc[oc] = fmaf(sw1[(oc * 3 + ic) * 9 + di * 3 + dj], v, acc[oc]);
                    }
                }
            }
#pragma unroll
            for (int oc = 0; oc < 6; oc++)
                g_h1[((b * 6 + oc) * 64 + i) * 64 + j] = leaky(acc[oc]);
        }
        __threadfence();
        __syncthreads();
        if (tid == 0) atomicAdd(&g_sync[SC1 + b], 1u);

        if (tid == 0) {
            while (atomicAdd(&g_sync[SC1 + b], 0u) < 4u) __nanosleep(64);
            __threadfence();
        }
        __syncthreads();

        // conv2, quarter q
        {
            const int i = q * 8 + (tid >> 5);
            const int j = tid & 31;
            const float* h1b = g_h1 + (size_t)b * 6 * 64 * 64;
            float acc[12];
#pragma unroll
            for (int oc = 0; oc < 12; oc++) acc[oc] = sb2[oc];
#pragma unroll
            for (int ic = 0; ic < 6; ic++) {
#pragma unroll
                for (int di = 0; di < 3; di++) {
                    const int yi = 2 * i + di - 1;
#pragma unroll
                    for (int dj = 0; dj < 3; dj++) {
                        const int yj = 2 * j + dj - 1;
                        float v = 0.f;
                        if (yi >= 0 && yj >= 0) v = h1b[(ic * 64 + yi) * 64 + yj];
#pragma unroll
                        for (int oc = 0; oc < 12; oc++)
                            acc[oc] = fmaf(sw2[(oc * 6 + ic) * 9 + di * 3 + dj], v, acc[oc]);
                    }
                }
            }
#pragma unroll
            for (int oc = 0; oc < 12; oc++)
                g_h2[((b * 12 + oc) * 32 + i) * 32 + j] = leaky(acc[oc]);
        }
        __threadfence();
        __syncthreads();
        if (tid == 0) atomicAdd(&g_sync[SC2 + b], 1u);

        if (q != 0) return;

        if (tid == 0) {
            while (atomicAdd(&g_sync[SC2 + b], 0u) < 4u) __nanosleep(64);
            __threadfence();
        }
        __syncthreads();

        // conv3
        {
            const int i = tid >> 4;
            const int j = tid & 15;
            const float* h2b = g_h2 + (size_t)b * 12 * 32 * 32;
            float acc[12];
#pragma unroll
            for (int oc = 0; oc < 12; oc++) acc[oc] = sb3[oc];
            for (int ic = 0; ic < 12; ic++) {
#pragma unroll
                for (int di = 0; di < 3; di++) {
                    const int yi = 2 * i + di - 1;
#pragma unroll
                    for (int dj = 0; dj < 3; dj++) {
                        const int yj = 2 * j + dj - 1;
                        float v = 0.f;
                        if (yi >= 0 && yj >= 0) v = h2b[(ic * 32 + yi) * 32 + yj];
#pragma unroll
                        for (int oc = 0; oc < 12; oc++)
                            acc[oc] = fmaf(sw3[(oc * 12 + ic) * 9 + di * 3 + dj], v, acc[oc]);
                    }
                }
            }
#pragma unroll
            for (int oc = 0; oc < 12; oc++)
                h3[(oc * 16 + i) * 16 + j] = leaky(acc[oc]);
        }
        __syncthreads();

        // conv4
        if (tid < 64) {
            const int i = tid >> 3;
            const int j = tid & 7;
            float acc[12];
#pragma unroll
            for (int oc = 0; oc < 12; oc++) acc[oc] = sb4[oc];
            for (int ic = 0; ic < 12; ic++) {
#pragma unroll
                for (int di = 0; di < 3; di++) {
                    const int yi = 2 * i + di - 1;
#pragma unroll
                    for (int dj = 0; dj < 3; dj++) {
                        const int yj = 2 * j + dj - 1;
                        float v = 0.f;
                        if (yi >= 0 && yj >= 0) v = h3[(ic * 16 + yi) * 16 + yj];
#pragma unroll
                        for (int oc = 0; oc < 12; oc++)
                            acc[oc] = fmaf(sw4[(oc * 12 + ic) * 9 + di * 3 + dj], v, acc[oc]);
                    }
                }
            }
#pragma unroll
            for (int oc = 0; oc < 12; oc++)
                h4[(oc * 8 + i) * 8 + j] = leaky(acc[oc]);
        }
        __syncthreads();

        // conv5
        if (tid < 96) {
            const int oc = tid >> 4;
            const int p  = tid & 15;
            const int i  = p >> 2;
            const int jj = p & 3;
            float acc = sb5[oc];
            for (int ic = 0; ic < 12; ic++) {
#pragma unroll
                for (int di = 0; di < 3; di++) {
                    const int yi = 2 * i + di - 1;
#pragma unroll
                    for (int dj = 0; dj < 3; dj++) {
                        const int yj = 2 * jj + dj - 1;
                        float v = 0.f;
                        if (yi >= 0 && yj >= 0) v = h4[(ic * 8 + yi) * 8 + yj];
                        acc = fmaf(sw5[(oc * 12 + ic) * 9 + di * 3 + dj], v, acc);
                    }
                }
            }
            h5[oc * 16 + p] = leaky(acc);
        }
        __syncthreads();

        // conv6 (1x1) + relu -> g_pal, publish SPR then SPALL
        if (tid < 48) {
            const int c = tid >> 4;
            const int k = tid & 15;
            float acc = sb6[c];
#pragma unroll
            for (int ic = 0; ic < 6; ic++)
                acc = fmaf(sw6[c * 6 + ic], h5[ic * 16 + k], acc);
            g_pal[b * 48 + c * 16 + k] = fmaxf(acc, 0.f);
            __threadfence();
        }
        __syncthreads();
        if (tid == 0) {
            atomicExch(&g_sync[SPR + b], 1u);
            atomicAdd(&g_sync[SPALL], 1u);
        }
        return;
    }

    // ---------------------------------------------------------------------
    // GATHER PATH: static tile. Loads first, non-blocking palette check,
    // inline paint or mask+publish. (Proven 35.7us shape.)
    // ---------------------------------------------------------------------
    const int gid = bid - NCONVBLK;
    const int b   = gid / GB_PER_B;
    const int blk = gid - b * GB_PER_B;
    const int p   = blk * NTHREADS + tid;
    const bool act = (p < HW4);

    __shared__ float4   spal4[16];
    __shared__ unsigned s_ready;
    __shared__ int      s_drain;
    __shared__ int      s_done;

    float4 l[16];
    if (act) {
        const float4* lg = reinterpret_cast<const float4*>(logits)
                           + (size_t)b * 16 * HW4 + p;
#pragma unroll
        for (int k = 0; k < 16; k++) l[k] = __ldcs(lg + (size_t)k * HW4);
    }

    if (tid == 0) {
        const unsigned r = atomicAdd(&g_sync[SPR + b], 0u);
        if (r) __threadfence();
        s_ready = r;
    }
    __syncthreads();
    const bool direct = (s_ready != 0u);
    if (direct && tid < 16) {
        const int k = tid;
        spal4[k] = make_float4(__ldcg(&g_pal[b * 48 + k]),
                               __ldcg(&g_pal[b * 48 + 16 + k]),
                               __ldcg(&g_pal[b * 48 + 32 + k]),
                               0.f);
    }
    __syncthreads();

    if (act) {
        float4 mx = l[0];
#pragma unroll
        for (int k = 1; k < 16; k++) {
            mx.x = fmaxf(mx.x, l[k].x);
            mx.y = fmaxf(mx.y, l[k].y);
            mx.z = fmaxf(mx.z, l[k].z);
            mx.w = fmaxf(mx.w, l[k].w);
        }
        unsigned mA = 0, mB = 0, mC = 0, mD = 0;
#pragma unroll
        for (int k = 0; k < 16; k++) {
            mA |= (l[k].x == mx.x) ? (1u << k) : 0u;
            mB |= (l[k].y == mx.y) ? (1u << k) : 0u;
            mC |= (l[k].z == mx.z) ? (1u << k) : 0u;
            mD |= (l[k].w == mx.w) ? (1u << k) : 0u;
        }

        if (direct) {
            float r0[4], r1[4], r2[4];
            unsigned ms[4] = { mA, mB, mC, mD };
#pragma unroll
            for (int px = 0; px < 4; px++) {
                unsigned bits = ms[px];
                float s0 = 0.f, s1 = 0.f, s2 = 0.f;
                while (bits) {
                    const int k = __ffs(bits) - 1;
                    bits &= bits - 1;
                    const float4 c = spal4[k];
                    s0 += c.x; s1 += c.y; s2 += c.z;
                }
                r0[px] = s0; r1[px] = s1; r2[px] = s2;
            }
            float4* o = reinterpret_cast<float4*>(out) + (size_t)(b * 3) * HW4 + p;
            __stcs(o,                    make_float4(r0[0], r0[1], r0[2], r0[3]));
            __stcs(o + HW4,              make_float4(r1[0], r1[1], r1[2], r1[3]));
            __stcs(o + 2 * (size_t)HW4,  make_float4(r2[0], r2[1], r2[2], r2[3]));
        } else {
            const unsigned long long m =
                (unsigned long long)mA
                | ((unsigned long long)mB << 16)
                | ((unsigned long long)mC << 32)
                | ((unsigned long long)mD << 48);
            g_mask[(size_t)b * HW4 + p] = m;
        }
    }

    // publish leftover entry (masks fenced before publication)
    if (!direct) {
        __threadfence();
        __syncthreads();
        if (tid == 0) {
            const unsigned idx = atomicAdd(&g_sync[SRESV], 1u);
            atomicExch(&g_sync[QBASE + idx], (unsigned)(gid + 1));
        }
    }
    __syncthreads();

    // mark tile done; detect the provably-last gather block
    __shared__ unsigned s_myfin;
    if (tid == 0) s_myfin = atomicAdd(&g_sync[SFIN], 1u);
    __syncthreads();
    const bool is_last = (s_myfin == (unsigned)(NGATHER - 1));

    if (!is_last) {
        // ---- opportunistic non-blocking pop: one attempt, never waits ----
        if (tid == 0) {
            s_drain = -1;
            if (atomicAdd(&g_sync[SPALL], 0u) == (unsigned)BATCH) {
                const unsigned ticket = atomicAdd(&g_sync[SDEQ], 1u);
                if (ticket < atomicAdd(&g_sync[SRESV], 0u)) {
                    const unsigned v = atomicExch(&g_sync[QBASE + ticket], SENT);
                    if (v != 0u && v != SENT) { __threadfence(); s_drain = (int)v - 1; }
                }
            }
        }
        __syncthreads();
        const int t = s_drain;
        if (t < 0) return;

        const int db   = t / GB_PER_B;
        const int dblk = t - db * GB_PER_B;
        const int dp   = dblk * NTHREADS + tid;

        if (tid < 16) {
            const int k = tid;
            spal4[k] = make_float4(g_pal[db * 48 + k],
                                   g_pal[db * 48 + 16 + k],
                                   g_pal[db * 48 + 32 + k],
                                   0.f);
        }
        __syncthreads();

        if (dp < HW4) {
            const unsigned long long m = g_mask[(size_t)db * HW4 + dp];
            float r0[4], r1[4], r2[4];
#pragma unroll
            for (int px = 0; px < 4; px++) {
                unsigned bits = (unsigned)((m >> (16 * px)) & 0xFFFFull);
                float s0 = 0.f, s1 = 0.f, s2 = 0.f;
                while (bits) {
                    const int k = __ffs(bits) - 1;
                    bits &= bits - 1;
                    const float4 c = spal4[k];
                    s0 += c.x; s1 += c.y; s2 += c.z;
                }
                r0[px] = s0; r1[px] = s1; r2[px] = s2;
            }
            float4* o = reinterpret_cast<float4*>(out) + (size_t)(db * 3) * HW4 + dp;
            o[0]               = make_float4(r0[0], r0[1], r0[2], r0[3]);
            o[HW4]             = make_float4(r1[0], r1[1], r1[2], r1[3]);
            o[2 * (size_t)HW4] = make_float4(r2[0], r2[1], r2[2], r2[3]);
        }
        __syncthreads();
        if (tid == 0) atomicAdd(&g_sync[SPAINT], 1u);
        return;
    }

    // ---- last gather block: sweep until painted == published ----
    // All publishes precede SFIN increments, so SRESV is final here.
    if (tid == 0) {
        while (atomicAdd(&g_sync[SPALL], 0u) < (unsigned)BATCH) __nanosleep(64);
        __threadfence();
    }
    __syncthreads();

    while (true) {
        if (tid == 0)
            s_done = (atomicAdd(&g_sync[SPAINT], 0u) ==
                      atomicAdd(&g_sync[SRESV], 0u)) ? 1 : 0;
        __syncthreads();
        if (s_done) break;

        const int n = (int)atomicAdd(&g_sync[SRESV], 0u);
        for (int idx = 0; idx < n; idx++) {
            if (tid == 0) {
                const unsigned v = atomicExch(&g_sync[QBASE + idx], SENT);
                s_drain = (v != 0u && v != SENT) ? (int)v - 1 : -1;
                if (s_drain >= 0) __threadfence();
            }
            __syncthreads();
            const int t = s_drain;
            if (t >= 0) {
                const int db   = t / GB_PER_B;
                const int dblk = t - db * GB_PER_B;
                const int dp   = dblk * NTHREADS + tid;

                if (tid < 16) {
                    const int k = tid;
                    spal4[k] = make_float4(g_pal[db * 48 + k],
                                           g_pal[db * 48 + 16 + k],
                                           g_pal[db * 48 + 32 + k],
                                           0.f);
                }
                __syncthreads();

                if (dp < HW4) {
                    const unsigned long long m = g_mask[(size_t)db * HW4 + dp];
                    float r0[4], r1[4], r2[4];
#pragma unroll
                    for (int px = 0; px < 4; px++) {
                        unsigned bits = (unsigned)((m >> (16 * px)) & 0xFFFFull);
                        float s0 = 0.f, s1 = 0.f, s2 = 0.f;
                        while (bits) {
                            const int k = __ffs(bits) - 1;
                            bits &= bits - 1;
                            const float4 c = spal4[k];
                            s0 += c.x; s1 += c.y; s2 += c.z;
                        }
                        r0[px] = s0; r1[px] = s1; r2[px] = s2;
                    }
                    float4* o = reinterpret_cast<float4*>(out) + (size_t)(db * 3) * HW4 + dp;
                    o[0]               = make_float4(r0[0], r0[1], r0[2], r0[3]);
                    o[HW4]             = make_float4(r1[0], r1[1], r1[2], r1[3]);
                    o[2 * (size_t)HW4] = make_float4(r2[0], r2[1], r2[2], r2[3]);
                }
                __syncthreads();
                if (tid == 0) atomicAdd(&g_sync[SPAINT], 1u);
            }
            __syncthreads();
        }
        if (tid == 0) __nanosleep(128);
        __syncthreads();
    }
}

// ---------------------------------------------------------------------------
extern "C" void kernel_launch(void* const* d_in, const int* in_sizes, int n_in,
                              void* d_out, int out_size) {
    (void)in_sizes; (void)n_in; (void)out_size;
    const float* x  = (const float*)d_in[0];
    const float* bl = (const float*)d_in[1];
    const float* w1 = (const float*)d_in[2];
    const float* b1 = (const float*)d_in[3];
    const float* w2 = (const float*)d_in[4];
    const float* b2 = (const float*)d_in[5];
    const float* w3 = (const float*)d_in[6];
    const float* b3 = (const float*)d_in[7];
    const float* w4 = (const float*)d_in[8];
    const float* b4 = (const float*)d_in[9];
    const float* w5 = (const float*)d_in[10];
    const float* b5 = (const float*)d_in[11];
    const float* w6 = (const float*)d_in[12];
    const float* b6 = (const float*)d_in[13];
    float* out = (float*)d_out;

    void* sync_ptr = nullptr;
    cudaGetSymbolAddress(&sync_ptr, g_sync);
    cudaMemsetAsync(sync_ptr, 0, (QBASE + NGATHER) * sizeof(unsigned));

    spnet_main_kernel<<<NCONVBLK + NGATHER, NTHREADS>>>(
        x, bl, w1, b1, w2, b2, w3, b3, w4, b4, w5, b5, w6, b6, out);
}

// round 16
// speedup vs baseline: 35.7679x; 35.7679x over previous
#include <cuda_runtime.h>
#include <cstdint>

// ---------------------------------------------------------------------------
// SPNet, v15: round-13 base + STATIC 1:1 rescue pairing (no queue, no sweep).
//
// Round-15 lesson: unbounded in-kernel sweeps/pop contention -> 2ms disaster.
// Every block must have a statically bounded exit.
//
// Structure:
//   main kernel: conv blocks 0..63 (proven), gather blocks with static tiles
//     (proven 16xfloat4 __ldcs shape). Fallback tiles set need-flag.
//     Blocks gid>=1256 additionally make ONE non-blocking rescue attempt on
//     victim gid-1256 (leftovers are always gids < ~1184): flag set + palette
//     ready -> exclusive claim (atomicExch) -> paint. Else leave for backstop.
//   backstop kernel: 296 blocks striding the flags; expected ~zero work.
// ---------------------------------------------------------------------------

#define BATCH      16
#define HW         160000         // 400*400
#define HW4        40000          // float4 per plane
#define GB_PER_B   157            // ceil(40000/256)
#define NGATHER    (BATCH * GB_PER_B)   // 2512
#define NCONVBLK   64
#define NTHREADS   256
#define RESCUE_OFF 1256
#define NBACK      296

// g_sync layout
#define SC1   0     // [0:16)  conv1 quarter counts
#define SC2   16    // [16:32) conv2 quarter counts
#define SPR   32    // [32:48) per-batch palette-ready
#define SNEED 48    // [48:48+NGATHER) per-tile needs-paint flag

__device__ float              g_h1[BATCH * 6  * 64 * 64];
__device__ float              g_h2[BATCH * 12 * 32 * 32];
__device__ float              g_pal[BATCH * 48];
__device__ unsigned long long g_mask[BATCH * HW4];
__device__ unsigned           g_sync[SNEED + NGATHER];

__device__ __forceinline__ float leaky(float v) {
    return (v >= 0.f) ? v : 0.01f * v;
}

// shared paint helper: paint tile t from g_mask using spal4 (already staged)
__device__ __forceinline__ void paint_tile_from_mask(
    float4* __restrict__ spal4, float* __restrict__ out, int t, int tid) {
    const int b   = t / GB_PER_B;
    const int blk = t - b * GB_PER_B;
    const int p   = blk * NTHREADS + tid;
    if (p >= HW4) return;

    const unsigned long long m = g_mask[(size_t)b * HW4 + p];
    float r0[4], r1[4], r2[4];
#pragma unroll
    for (int px = 0; px < 4; px++) {
        unsigned bits = (unsigned)((m >> (16 * px)) & 0xFFFFull);
        float s0 = 0.f, s1 = 0.f, s2 = 0.f;
        while (bits) {
            const int k = __ffs(bits) - 1;
            bits &= bits - 1;
            const float4 c = spal4[k];
            s0 += c.x; s1 += c.y; s2 += c.z;
        }
        r0[px] = s0; r1[px] = s1; r2[px] = s2;
    }
    float4* o = reinterpret_cast<float4*>(out) + (size_t)(b * 3) * HW4 + p;
    o[0]               = make_float4(r0[0], r0[1], r0[2], r0[3]);
    o[HW4]             = make_float4(r1[0], r1[1], r1[2], r1[3]);
    o[2 * (size_t)HW4] = make_float4(r2[0], r2[1], r2[2], r2[3]);
}

// ===========================================================================
// Kernel 1: conv blocks 0..63; gather blocks with static tiles + rescue.
// ===========================================================================
__global__ void __launch_bounds__(NTHREADS, 2)
spnet_main_kernel(const float* __restrict__ x,
                  const float* __restrict__ logits,
                  const float* __restrict__ w1, const float* __restrict__ b1,
                  const float* __restrict__ w2, const float* __restrict__ b2,
                  const float* __restrict__ w3, const float* __restrict__ b3,
                  const float* __restrict__ w4, const float* __restrict__ b4,
                  const float* __restrict__ w5, const float* __restrict__ b5,
                  const float* __restrict__ w6, const float* __restrict__ b6,
                  float* __restrict__ out) {
    const int bid = blockIdx.x;
    const int tid = threadIdx.x;

    // ---------------------------------------------------------------------
    // CONV PATH (blocks 0..63) — identical to the proven 46.8us version.
    // ---------------------------------------------------------------------
    if (bid < NCONVBLK) {
        const int b = bid >> 2;
        const int q = bid & 3;

        __shared__ float sw1[162], sb1[6];
        __shared__ float sw2[648], sb2[12];
        __shared__ float sw3[1296], sb3[12];
        __shared__ float sw4[1296], sb4[12];
        __shared__ float sw5[648], sb5[6];
        __shared__ float sw6[18], sb6[3];
        __shared__ float h3[12 * 16 * 16];
        __shared__ float h4[12 * 8 * 8];
        __shared__ float h5[6 * 16];

        for (int i = tid; i < 162; i += NTHREADS) sw1[i] = w1[i];
        for (int i = tid; i < 648; i += NTHREADS) { sw2[i] = w2[i]; sw5[i] = w5[i]; }
        for (int i = tid; i < 1296; i += NTHREADS) { sw3[i] = w3[i]; sw4[i] = w4[i]; }
        if (tid < 18) sw6[tid] = w6[tid];
        if (tid < 12) { sb2[tid] = b2[tid]; sb3[tid] = b3[tid]; sb4[tid] = b4[tid]; }
        if (tid < 6)  { sb1[tid] = b1[tid]; sb5[tid] = b5[tid]; }
        if (tid < 3)  sb6[tid] = b6[tid];
        __syncthreads();

        // conv1, quarter q
        for (int pos = tid; pos < 1024; pos += NTHREADS) {
            const int i = q * 16 + (pos >> 6);
            const int j = pos & 63;
            float acc[6];
#pragma unroll
            for (int oc = 0; oc < 6; oc++) acc[oc] = sb1[oc];
#pragma unroll
            for (int ic = 0; ic < 3; ic++) {
                const float* xp = x + (size_t)(b * 3 + ic) * HW;
#pragma unroll
                for (int di = 0; di < 3; di++) {
                    const int yi = 2 * i + di - 1;
#pragma unroll
                    for (int dj = 0; dj < 3; dj++) {
                        const int yj = 2 * j + dj - 1;
                        float v = 0.f;
                        if (yi >= 0 && yj >= 0) v = xp[yi * 400 + yj];
#pragma unroll
                        for (int oc = 0; oc < 6; oc++)
                            acc[oc] = fmaf(sw1[(oc * 3 + ic) * 9 + di * 3 + dj], v, acc[oc]);
                    }
                }
            }
#pragma unroll
            for (int oc = 0; oc < 6; oc++)
                g_h1[((b * 6 + oc) * 64 + i) * 64 + j] = leaky(acc[oc]);
        }
        __threadfence();
        __syncthreads();
        if (tid == 0) atomicAdd(&g_sync[SC1 + b], 1u);

        if (tid == 0) {
            while (atomicAdd(&g_sync[SC1 + b], 0u) < 4u) __nanosleep(64);
            __threadfence();
        }
        __syncthreads();

        // conv2, quarter q
        {
            const int i = q * 8 + (tid >> 5);
            const int j = tid & 31;
            const float* h1b = g_h1 + (size_t)b * 6 * 64 * 64;
            float acc[12];
#pragma unroll
            for (int oc = 0; oc < 12; oc++) acc[oc] = sb2[oc];
#pragma unroll
            for (int ic = 0; ic < 6; ic++) {
#pragma unroll
                for (int di = 0; di < 3; di++) {
                    const int yi = 2 * i + di - 1;
#pragma unroll
                    for (int dj = 0; dj < 3; dj++) {
                        const int yj = 2 * j + dj - 1;
                        float v = 0.f;
                        if (yi >= 0 && yj >= 0) v = h1b[(ic * 64 + yi) * 64 + yj];
#pragma unroll
                        for (int oc = 0; oc < 12; oc++)
                            acc[oc] = fmaf(sw2[(oc * 6 + ic) * 9 + di * 3 + dj], v, acc[oc]);
                    }
                }
            }
#pragma unroll
            for (int oc = 0; oc < 12; oc++)
                g_h2[((b * 12 + oc) * 32 + i) * 32 + j] = leaky(acc[oc]);
        }
        __threadfence();
        __syncthreads();
        if (tid == 0) atomicAdd(&g_sync[SC2 + b], 1u);

        if (q != 0) return;

        if (tid == 0) {
            while (atomicAdd(&g_sync[SC2 + b], 0u) < 4u) __nanosleep(64);
            __threadfence();
        }
        __syncthreads();

        // conv3
        {
            const int i = tid >> 4;
            const int j = tid & 15;
            const float* h2b = g_h2 + (size_t)b * 12 * 32 * 32;
            float acc[12];
#pragma unroll
            for (int oc = 0; oc < 12; oc++) acc[oc] = sb3[oc];
            for (int ic = 0; ic < 12; ic++) {
#pragma unroll
                for (int di = 0; di < 3; di++) {
                    const int yi = 2 * i + di - 1;
#pragma unroll
                    for (int dj = 0; dj < 3; dj++) {
                        const int yj = 2 * j + dj - 1;
                        float v = 0.f;
                        if (yi >= 0 && yj >= 0) v = h2b[(ic * 32 + yi) * 32 + yj];
#pragma unroll
                        for (int oc = 0; oc < 12; oc++)
                            acc[oc] = fmaf(sw3[(oc * 12 + ic) * 9 + di * 3 + dj], v, acc[oc]);
                    }
                }
            }
#pragma unroll
            for (int oc = 0; oc < 12; oc++)
                h3[(oc * 16 + i) * 16 + j] = leaky(acc[oc]);
        }
        __syncthreads();

        // conv4
        if (tid < 64) {
            const int i = tid >> 3;
            const int j = tid & 7;
            float acc[12];
#pragma unroll
            for (int oc = 0; oc < 12; oc++) acc[oc] = sb4[oc];
            for (int ic = 0; ic < 12; ic++) {
#pragma unroll
                for (int di = 0; di < 3; di++) {
                    const int yi = 2 * i + di - 1;
#pragma unroll
                    for (int dj = 0; dj < 3; dj++) {
                        const int yj = 2 * j + dj - 1;
                        float v = 0.f;
                        if (yi >= 0 && yj >= 0) v = h3[(ic * 16 + yi) * 16 + yj];
#pragma unroll
                        for (int oc = 0; oc < 12; oc++)
                            acc[oc] = fmaf(sw4[(oc * 12 + ic) * 9 + di * 3 + dj], v, acc[oc]);
                    }
                }
            }
#pragma unroll
            for (int oc = 0; oc < 12; oc++)
                h4[(oc * 8 + i) * 8 + j] = leaky(acc[oc]);
        }
        __syncthreads();

        // conv5
        if (tid < 96) {
            const int oc = tid >> 4;
            const int p  = tid & 15;
            const int i  = p >> 2;
            const int jj = p & 3;
            float acc = sb5[oc];
            for (int ic = 0; ic < 12; ic++) {
#pragma unroll
                for (int di = 0; di < 3; di++) {
                    const int yi = 2 * i + di - 1;
#pragma unroll
                    for (int dj = 0; dj < 3; dj++) {
                        const int yj = 2 * jj + dj - 1;
                        float v = 0.f;
                        if (yi >= 0 && yj >= 0) v = h4[(ic * 8 + yi) * 8 + yj];
                        acc = fmaf(sw5[(oc * 12 + ic) * 9 + di * 3 + dj], v, acc);
                    }
                }
            }
            h5[oc * 16 + p] = leaky(acc);
        }
        __syncthreads();

        // conv6 (1x1) + relu -> g_pal, publish
        if (tid < 48) {
            const int c = tid >> 4;
            const int k = tid & 15;
            float acc = sb6[c];
#pragma unroll
            for (int ic = 0; ic < 6; ic++)
                acc = fmaf(sw6[c * 6 + ic], h5[ic * 16 + k], acc);
            g_pal[b * 48 + c * 16 + k] = fmaxf(acc, 0.f);
            __threadfence();
        }
        __syncthreads();
        if (tid == 0) atomicExch(&g_sync[SPR + b], 1u);
        return;
    }

    // ---------------------------------------------------------------------
    // GATHER PATH: static tile (proven shape), then one static rescue try.
    // ---------------------------------------------------------------------
    const int gid = bid - NCONVBLK;
    const int b   = gid / GB_PER_B;
    const int blk = gid - b * GB_PER_B;
    const int p   = blk * NTHREADS + tid;
    const bool act = (p < HW4);

    __shared__ float4   spal4[16];
    __shared__ unsigned s_ready;
    __shared__ int      s_resc;

    float4 l[16];
    if (act) {
        const float4* lg = reinterpret_cast<const float4*>(logits)
                           + (size_t)b * 16 * HW4 + p;
#pragma unroll
        for (int k = 0; k < 16; k++) l[k] = __ldcs(lg + (size_t)k * HW4);
    }

    if (tid == 0) {
        const unsigned r = atomicAdd(&g_sync[SPR + b], 0u);
        if (r) __threadfence();
        s_ready = r;
    }
    __syncthreads();
    const bool direct = (s_ready != 0u);
    if (direct && tid < 16) {
        const int k = tid;
        spal4[k] = make_float4(__ldcg(&g_pal[b * 48 + k]),
                               __ldcg(&g_pal[b * 48 + 16 + k]),
                               __ldcg(&g_pal[b * 48 + 32 + k]),
                               0.f);
    }
    __syncthreads();

    if (act) {
        float4 mx = l[0];
#pragma unroll
        for (int k = 1; k < 16; k++) {
            mx.x = fmaxf(mx.x, l[k].x);
            mx.y = fmaxf(mx.y, l[k].y);
            mx.z = fmaxf(mx.z, l[k].z);
            mx.w = fmaxf(mx.w, l[k].w);
        }
        unsigned mA = 0, mB = 0, mC = 0, mD = 0;
#pragma unroll
        for (int k = 0; k < 16; k++) {
            mA |= (l[k].x == mx.x) ? (1u << k) : 0u;
            mB |= (l[k].y == mx.y) ? (1u << k) : 0u;
            mC |= (l[k].z == mx.z) ? (1u << k) : 0u;
            mD |= (l[k].w == mx.w) ? (1u << k) : 0u;
        }

        if (direct) {
            float r0[4], r1[4], r2[4];
            unsigned ms[4] = { mA, mB, mC, mD };
#pragma unroll
            for (int px = 0; px < 4; px++) {
                unsigned bits = ms[px];
                float s0 = 0.f, s1 = 0.f, s2 = 0.f;
                while (bits) {
                    const int k = __ffs(bits) - 1;
                    bits &= bits - 1;
                    const float4 c = spal4[k];
                    s0 += c.x; s1 += c.y; s2 += c.z;
                }
                r0[px] = s0; r1[px] = s1; r2[px] = s2;
            }
            float4* o = reinterpret_cast<float4*>(out) + (size_t)(b * 3) * HW4 + p;
            __stcs(o,                    make_float4(r0[0], r0[1], r0[2], r0[3]));
            __stcs(o + HW4,              make_float4(r1[0], r1[1], r1[2], r1[3]));
            __stcs(o + 2 * (size_t)HW4,  make_float4(r2[0], r2[1], r2[2], r2[3]));
        } else {
            const unsigned long long m =
                (unsigned long long)mA
                | ((unsigned long long)mB << 16)
                | ((unsigned long long)mC << 32)
                | ((unsigned long long)mD << 48);
            g_mask[(size_t)b * HW4 + p] = m;
        }
    }

    // publish need-flag (masks fenced before publication)
    if (!direct) {
        __threadfence();
        __syncthreads();
        if (tid == 0) atomicExch(&g_sync[SNEED + gid], 1u);
    }
    __syncthreads();

    // ---- static rescue: ONE non-blocking attempt on victim gid-RESCUE_OFF.
    const int victim = gid - RESCUE_OFF;
    if (victim < 0) return;

    if (tid == 0) {
        s_resc = 0;
        const int vb = victim / GB_PER_B;
        if (atomicAdd(&g_sync[SPR + vb], 0u) != 0u) {          // palette ready
            if (atomicExch(&g_sync[SNEED + victim], 0u) == 1u) {  // exclusive claim
                __threadfence();
                s_resc = 1;
            }
        }
    }
    __syncthreads();
    if (!s_resc) return;

    {
        const int vb = victim / GB_PER_B;
        if (tid < 16) {
            const int k = tid;
            spal4[k] = make_float4(g_pal[vb * 48 + k],
                                   g_pal[vb * 48 + 16 + k],
                                   g_pal[vb * 48 + 32 + k],
                                   0.f);
        }
        __syncthreads();
        paint_tile_from_mask(spal4, out, victim, tid);
    }
}

// ===========================================================================
// Kernel 2: backstop. 296 blocks striding the need-flags; expected ~0 work.
// ===========================================================================
__global__ void __launch_bounds__(NTHREADS)
spnet_backstop_kernel(float* __restrict__ out) {
    __shared__ float4 spal4[16];
    __shared__ int    s_need;

    for (int gid = blockIdx.x; gid < NGATHER; gid += NBACK) {
        __syncthreads();
        if (threadIdx.x == 0)
            s_need = (int)atomicAdd(&g_sync[SNEED + gid], 0u);
        __syncthreads();
        if (!s_need) continue;

        __threadfence();
        const int b = gid / GB_PER_B;
        if (threadIdx.x < 16) {
            const int k = threadIdx.x;
            spal4[k] = make_float4(g_pal[b * 48 + k],
                                   g_pal[b * 48 + 16 + k],
                                   g_pal[b * 48 + 32 + k],
                                   0.f);
        }
        __syncthreads();
        paint_tile_from_mask(spal4, out, gid, threadIdx.x);
    }
}

// ---------------------------------------------------------------------------
extern "C" void kernel_launch(void* const* d_in, const int* in_sizes, int n_in,
                              void* d_out, int out_size) {
    (void)in_sizes; (void)n_in; (void)out_size;
    const float* x  = (const float*)d_in[0];
    const float* bl = (const float*)d_in[1];
    const float* w1 = (const float*)d_in[2];
    const float* b1 = (const float*)d_in[3];
    const float* w2 = (const float*)d_in[4];
    const float* b2 = (const float*)d_in[5];
    const float* w3 = (const float*)d_in[6];
    const float* b3 = (const float*)d_in[7];
    const float* w4 = (const float*)d_in[8];
    const float* b4 = (const float*)d_in[9];
    const float* w5 = (const float*)d_in[10];
    const float* b5 = (const float*)d_in[11];
    const float* w6 = (const float*)d_in[12];
    const float* b6 = (const float*)d_in[13];
    float* out = (float*)d_out;

    void* sync_ptr = nullptr;
    cudaGetSymbolAddress(&sync_ptr, g_sync);
    cudaMemsetAsync(sync_ptr, 0, (SNEED + NGATHER) * sizeof(unsigned));

    spnet_main_kernel<<<NCONVBLK + NGATHER, NTHREADS>>>(
        x, bl, w1, b1, w2, b2, w3, b3, w4, b4, w5, b5, w6, b6, out);
    spnet_backstop_kernel<<<NBACK, NTHREADS>>>(out);
}

// round 17
// speedup vs baseline: 45.5786x; 1.2743x over previous
#include <cuda_runtime.h>
#include <cstdint>

// ---------------------------------------------------------------------------
// SPNet, v16: EXACT round-13 main kernel (46.8us best: conv hybrid + inline
// paint + compact leftover queue) + single-wave front-batched paint kernel.
//
// Round-16 lesson: striding backstop = serial latency chains (19us). The
// paint pass must obey the same law as the gather: ONE wave, all loads
// front-batched. 296 blocks, <=9 queue slots each, masks loaded with MLP=9.
// ---------------------------------------------------------------------------

#define BATCH    16
#define HW       160000         // 400*400
#define HW4      40000          // float4 per plane
#define GB_PER_B 157            // ceil(40000/256)
#define NGATHER  (BATCH * GB_PER_B)   // 2512
#define NCONVBLK 64
#define NTHREADS 256
#define NPAINT   296            // one full wave
#define MAXE     9              // ceil(2512/296)

__device__ float              g_h1[BATCH * 6  * 64 * 64];
__device__ float              g_h2[BATCH * 12 * 32 * 32];
__device__ float              g_pal[BATCH * 48];
__device__ unsigned long long g_mask[BATCH * HW4];
// g_sync: [0:16) conv1 count, [16:32) conv2 count, [32:48) pal-ready,
//         [48] queue counter.
__device__ unsigned           g_sync[49];
__device__ int                g_queue[NGATHER];

__device__ __forceinline__ float leaky(float v) {
    return (v >= 0.f) ? v : 0.01f * v;
}

// ===========================================================================
// Kernel 1: blocks 0..63 conv pipeline; blocks 64.. gather (inline paint or
// mask+enqueue). BYTE-IDENTICAL to the proven 46.8us round-13 kernel.
// ===========================================================================
__global__ void __launch_bounds__(NTHREADS, 2)
spnet_main_kernel(const float* __restrict__ x,
                  const float* __restrict__ logits,
                  const float* __restrict__ w1, const float* __restrict__ b1,
                  const float* __restrict__ w2, const float* __restrict__ b2,
                  const float* __restrict__ w3, const float* __restrict__ b3,
                  const float* __restrict__ w4, const float* __restrict__ b4,
                  const float* __restrict__ w5, const float* __restrict__ b5,
                  const float* __restrict__ w6, const float* __restrict__ b6,
                  float* __restrict__ out) {
    const int bid = blockIdx.x;
    const int tid = threadIdx.x;

    if (bid < NCONVBLK) {
        const int b = bid >> 2;
        const int q = bid & 3;

        __shared__ float sw1[162], sb1[6];
        __shared__ float sw2[648], sb2[12];
        __shared__ float sw3[1296], sb3[12];
        __shared__ float sw4[1296], sb4[12];
        __shared__ float sw5[648], sb5[6];
        __shared__ float sw6[18], sb6[3];
        __shared__ float h3[12 * 16 * 16];
        __shared__ float h4[12 * 8 * 8];
        __shared__ float h5[6 * 16];

        for (int i = tid; i < 162; i += NTHREADS) sw1[i] = w1[i];
        for (int i = tid; i < 648; i += NTHREADS) { sw2[i] = w2[i]; sw5[i] = w5[i]; }
        for (int i = tid; i < 1296; i += NTHREADS) { sw3[i] = w3[i]; sw4[i] = w4[i]; }
        if (tid < 18) sw6[tid] = w6[tid];
        if (tid < 12) { sb2[tid] = b2[tid]; sb3[tid] = b3[tid]; sb4[tid] = b4[tid]; }
        if (tid < 6)  { sb1[tid] = b1[tid]; sb5[tid] = b5[tid]; }
        if (tid < 3)  sb6[tid] = b6[tid];
        __syncthreads();

        // conv1, quarter q
        for (int pos = tid; pos < 1024; pos += NTHREADS) {
            const int i = q * 16 + (pos >> 6);
            const int j = pos & 63;
            float acc[6];
#pragma unroll
            for (int oc = 0; oc < 6; oc++) acc[oc] = sb1[oc];
#pragma unroll
            for (int ic = 0; ic < 3; ic++) {
                const float* xp = x + (size_t)(b * 3 + ic) * HW;
#pragma unroll
                for (int di = 0; di < 3; di++) {
                    const int yi = 2 * i + di - 1;
#pragma unroll
                    for (int dj = 0; dj < 3; dj++) {
                        const int yj = 2 * j + dj - 1;
                        float v = 0.f;
                        if (yi >= 0 && yj >= 0) v = xp[yi * 400 + yj];
#pragma unroll
                        for (int oc = 0; oc < 6; oc++)
                            acc[oc] = fmaf(sw1[(oc * 3 + ic) * 9 + di * 3 + dj], v, acc[oc]);
                    }
                }
            }
#pragma unroll
            for (int oc = 0; oc < 6; oc++)
                g_h1[((b * 6 + oc) * 64 + i) * 64 + j] = leaky(acc[oc]);
        }
        __threadfence();
        __syncthreads();
        if (tid == 0) atomicAdd(&g_sync[b], 1u);

        if (tid == 0) {
            while (atomicAdd(&g_sync[b], 0u) < 4u) __nanosleep(64);
            __threadfence();
        }
        __syncthreads();

        // conv2, quarter q
        {
            const int i = q * 8 + (tid >> 5);
            const int j = tid & 31;
            const float* h1b = g_h1 + (size_t)b * 6 * 64 * 64;
            float acc[12];
#pragma unroll
            for (int oc = 0; oc < 12; oc++) acc[oc] = sb2[oc];
#pragma unroll
            for (int ic = 0; ic < 6; ic++) {
#pragma unroll
                for (int di = 0; di < 3; di++) {
                    const int yi = 2 * i + di - 1;
#pragma unroll
                    for (int dj = 0; dj < 3; dj++) {
                        const int yj = 2 * j + dj - 1;
                        float v = 0.f;
                        if (yi >= 0 && yj >= 0) v = h1b[(ic * 64 + yi) * 64 + yj];
#pragma unroll
                        for (int oc = 0; oc < 12; oc++)
                            acc[oc] = fmaf(sw2[(oc * 6 + ic) * 9 + di * 3 + dj], v, acc[oc]);
                    }
                }
            }
#pragma unroll
            for (int oc = 0; oc < 12; oc++)
                g_h2[((b * 12 + oc) * 32 + i) * 32 + j] = leaky(acc[oc]);
        }
        __threadfence();
        __syncthreads();
        if (tid == 0) atomicAdd(&g_sync[16 + b], 1u);

        if (q != 0) return;

        if (tid == 0) {
            while (atomicAdd(&g_sync[16 + b], 0u) < 4u) __nanosleep(64);
            __threadfence();
        }
        __syncthreads();

        // conv3
        {
            const int i = tid >> 4;
            const int j = tid & 15;
            const float* h2b = g_h2 + (size_t)b * 12 * 32 * 32;
            float acc[12];
#pragma unroll
            for (int oc = 0; oc < 12; oc++) acc[oc] = sb3[oc];
            for (int ic = 0; ic < 12; ic++) {
#pragma unroll
                for (int di = 0; di < 3; di++) {
                    const int yi = 2 * i + di - 1;
#pragma unroll
                    for (int dj = 0; dj < 3; dj++) {
                        const int yj = 2 * j + dj - 1;
                        float v = 0.f;
                        if (yi >= 0 && yj >= 0) v = h2b[(ic * 32 + yi) * 32 + yj];
#pragma unroll
                        for (int oc = 0; oc < 12; oc++)
                            acc[oc] = fmaf(sw3[(oc * 12 + ic) * 9 + di * 3 + dj], v, acc[oc]);
                    }
                }
            }
#pragma unroll
            for (int oc = 0; oc < 12; oc++)
                h3[(oc * 16 + i) * 16 + j] = leaky(acc[oc]);
        }
        __syncthreads();

        // conv4
        if (tid < 64) {
            const int i = tid >> 3;
            const int j = tid & 7;
            float acc[12];
#pragma unroll
            for (int oc = 0; oc < 12; oc++) acc[oc] = sb4[oc];
            for (int ic = 0; ic < 12; ic++) {
#pragma unroll
                for (int di = 0; di < 3; di++) {
                    const int yi = 2 * i + di - 1;
#pragma unroll
                    for (int dj = 0; dj < 3; dj++) {
                        const int yj = 2 * j + dj - 1;
                        float v = 0.f;
                        if (yi >= 0 && yj >= 0) v = h3[(ic * 16 + yi) * 16 + yj];
#pragma unroll
                        for (int oc = 0; oc < 12; oc++)
                            acc[oc] = fmaf(sw4[(oc * 12 + ic) * 9 + di * 3 + dj], v, acc[oc]);
                    }
                }
            }
#pragma unroll
            for (int oc = 0; oc < 12; oc++)
                h4[(oc * 8 + i) * 8 + j] = leaky(acc[oc]);
        }
        __syncthreads();

        // conv5
        if (tid < 96) {
            const int oc = tid >> 4;
            const int p  = tid & 15;
            const int i  = p >> 2;
            const int jj = p & 3;
            float acc = sb5[oc];
            for (int ic = 0; ic < 12; ic++) {
#pragma unroll
                for (int di = 0; di < 3; di++) {
                    const int yi = 2 * i + di - 1;
#pragma unroll
                    for (int dj = 0; dj < 3; dj++) {
                        const int yj = 2 * jj + dj - 1;
                        float v = 0.f;
                        if (yi >= 0 && yj >= 0) v = h4[(ic * 8 + yi) * 8 + yj];
                        acc = fmaf(sw5[(oc * 12 + ic) * 9 + di * 3 + dj], v, acc);
                    }
                }
            }
            h5[oc * 16 + p] = leaky(acc);
        }
        __syncthreads();

        // conv6 (1x1) + relu -> g_pal, publish pal-ready
        if (tid < 48) {
            const int c = tid >> 4;
            const int k = tid & 15;
            float acc = sb6[c];
#pragma unroll
            for (int ic = 0; ic < 6; ic++)
                acc = fmaf(sw6[c * 6 + ic], h5[ic * 16 + k], acc);
            g_pal[b * 48 + c * 16 + k] = fmaxf(acc, 0.f);
            __threadfence();
        }
        __syncthreads();
        if (tid == 0) atomicExch(&g_sync[32 + b], 1u);
        return;
    }

    // ---------------------------------------------------------------------
    // GATHER PATH (identical to round 13)
    // ---------------------------------------------------------------------
    const int gid = bid - NCONVBLK;
    const int b   = gid / GB_PER_B;
    const int blk = gid - b * GB_PER_B;
    const int p   = blk * NTHREADS + tid;
    const bool act = (p < HW4);

    __shared__ float4   spal4[16];
    __shared__ unsigned s_ready;

    float4 l[16];
    if (act) {
        const float4* lg = reinterpret_cast<const float4*>(logits)
                           + (size_t)b * 16 * HW4 + p;
#pragma unroll
        for (int k = 0; k < 16; k++) l[k] = __ldcs(lg + (size_t)k * HW4);
    }

    if (tid == 0) {
        const unsigned r = atomicAdd(&g_sync[32 + b], 0u);
        if (r) __threadfence();
        s_ready = r;
    }
    __syncthreads();
    const bool direct = (s_ready != 0u);
    if (direct && tid < 16) {
        const int k = tid;
        spal4[k] = make_float4(__ldcg(&g_pal[b * 48 + k]),
                               __ldcg(&g_pal[b * 48 + 16 + k]),
                               __ldcg(&g_pal[b * 48 + 32 + k]),
                               0.f);
    }
    __syncthreads();

    if (act) {
        float4 mx = l[0];
#pragma unroll
        for (int k = 1; k < 16; k++) {
            mx.x = fmaxf(mx.x, l[k].x);
            mx.y = fmaxf(mx.y, l[k].y);
            mx.z = fmaxf(mx.z, l[k].z);
            mx.w = fmaxf(mx.w, l[k].w);
        }

        unsigned mA = 0, mB = 0, mC = 0, mD = 0;
#pragma unroll
        for (int k = 0; k < 16; k++) {
            mA |= (l[k].x == mx.x) ? (1u << k) : 0u;
            mB |= (l[k].y == mx.y) ? (1u << k) : 0u;
            mC |= (l[k].z == mx.z) ? (1u << k) : 0u;
            mD |= (l[k].w == mx.w) ? (1u << k) : 0u;
        }

        if (direct) {
            float r0[4], r1[4], r2[4];
            unsigned ms[4] = { mA, mB, mC, mD };
#pragma unroll
            for (int px = 0; px < 4; px++) {
                unsigned bits = ms[px];
                float s0 = 0.f, s1 = 0.f, s2 = 0.f;
                while (bits) {
                    const int k = __ffs(bits) - 1;
                    bits &= bits - 1;
                    const float4 c = spal4[k];
                    s0 += c.x; s1 += c.y; s2 += c.z;
                }
                r0[px] = s0; r1[px] = s1; r2[px] = s2;
            }
            float4* o = reinterpret_cast<float4*>(out) + (size_t)(b * 3) * HW4 + p;
            __stcs(o,                    make_float4(r0[0], r0[1], r0[2], r0[3]));
            __stcs(o + HW4,              make_float4(r1[0], r1[1], r1[2], r1[3]));
            __stcs(o + 2 * (size_t)HW4,  make_float4(r2[0], r2[1], r2[2], r2[3]));
        } else {
            const unsigned long long m =
                (unsigned long long)mA
                | ((unsigned long long)mB << 16)
                | ((unsigned long long)mC << 32)
                | ((unsigned long long)mD << 48);
            g_mask[(size_t)b * HW4 + p] = m;
        }
    }

    if (!direct && tid == 0) {
        __threadfence();
        const unsigned idx = atomicAdd(&g_sync[48], 1u);
        g_queue[idx] = gid;
    }
}

// ===========================================================================
// Kernel 2: single-wave front-batched paint. 296 blocks; block i owns queue
// slots i, i+296, ... (<=9). All mask loads issued independently (MLP=9).
// ===========================================================================
__global__ void __launch_bounds__(NTHREADS)
spnet_paint_kernel(float* __restrict__ out) {
    const int bid = blockIdx.x;
    const int tid = threadIdx.x;

    __shared__ float4 spal[MAXE][16];
    __shared__ int    stile[MAXE];

    const int n = (int)__ldcg(&g_sync[48]);

    // stage my queue entries (threads 0..MAXE-1, independent loads)
    if (tid < MAXE) {
        const int idx = bid + tid * NPAINT;
        stile[tid] = (idx < n) ? __ldcg(&g_queue[idx]) : -1;
    }
    __syncthreads();

    // front-batch: issue ALL mask loads independently
    unsigned long long m[MAXE];
    int pp[MAXE], bb[MAXE];
#pragma unroll
    for (int k = 0; k < MAXE; k++) {
        const int t = stile[k];
        if (t >= 0) {
            bb[k] = t / GB_PER_B;
            const int blk = t - bb[k] * GB_PER_B;
            pp[k] = blk * NTHREADS + tid;
            m[k] = (pp[k] < HW4) ? __ldcg(&g_mask[(size_t)bb[k] * HW4 + pp[k]]) : 0ull;
        } else {
            m[k] = 0ull; pp[k] = HW4; bb[k] = 0;
        }
    }

    // stage palettes for all entries in parallel (144 threads busy)
    if (tid < MAXE * 16) {
        const int k = tid >> 4;
        const int c = tid & 15;
        const int t = stile[k];
        if (t >= 0) {
            const int b = t / GB_PER_B;
            spal[k][c] = make_float4(__ldcg(&g_pal[b * 48 + c]),
                                     __ldcg(&g_pal[b * 48 + 16 + c]),
                                     __ldcg(&g_pal[b * 48 + 32 + c]),
                                     0.f);
        }
    }
    __syncthreads();

    // paint
#pragma unroll
    for (int k = 0; k < MAXE; k++) {
        if (stile[k] < 0 || pp[k] >= HW4) continue;
        float r0[4], r1[4], r2[4];
#pragma unroll
        for (int px = 0; px < 4; px++) {
            unsigned bits = (unsigned)((m[k] >> (16 * px)) & 0xFFFFull);
            float s0 = 0.f, s1 = 0.f, s2 = 0.f;
            while (bits) {
                const int c = __ffs(bits) - 1;
                bits &= bits - 1;
                const float4 pc = spal[k][c];
                s0 += pc.x; s1 += pc.y; s2 += pc.z;
            }
            r0[px] = s0; r1[px] = s1; r2[px] = s2;
        }
        float4* o = reinterpret_cast<float4*>(out)
                    + (size_t)(bb[k] * 3) * HW4 + pp[k];
        o[0]               = make_float4(r0[0], r0[1], r0[2], r0[3]);
        o[HW4]             = make_float4(r1[0], r1[1], r1[2], r1[3]);
        o[2 * (size_t)HW4] = make_float4(r2[0], r2[1], r2[2], r2[3]);
    }
}

// ---------------------------------------------------------------------------
extern "C" void kernel_launch(void* const* d_in, const int* in_sizes, int n_in,
                              void* d_out, int out_size) {
    (void)in_sizes; (void)n_in; (void)out_size;
    const float* x  = (const float*)d_in[0];
    const float* bl = (const float*)d_in[1];
    const float* w1 = (const float*)d_in[2];
    const float* b1 = (const float*)d_in[3];
    const float* w2 = (const float*)d_in[4];
    const float* b2 = (const float*)d_in[5];
    const float* w3 = (const float*)d_in[6];
    const float* b3 = (const float*)d_in[7];
    const float* w4 = (const float*)d_in[8];
    const float* b4 = (const float*)d_in[9];
    const float* w5 = (const float*)d_in[10];
    const float* b5 = (const float*)d_in[11];
    const float* w6 = (const float*)d_in[12];
    const float* b6 = (const float*)d_in[13];
    float* out = (float*)d_out;

    void* sync_ptr = nullptr;
    cudaGetSymbolAddress(&sync_ptr, g_sync);
    cudaMemsetAsync(sync_ptr, 0, 49 * sizeof(unsigned));

    spnet_main_kernel<<<NCONVBLK + NGATHER, NTHREADS>>>(
        x, bl, w1, b1, w2, b2, w3, b3, w4, b4, w5, b5, w6, b6, out);
    spnet_paint_kernel<<<NPAINT, NTHREADS>>>(out);
}